// round 4
// baseline (speedup 1.0000x reference)
#include <cuda_runtime.h>
#include <cuda_bf16.h>

#define NPW 16
#define M   64
#define NT  672            // 21 warps; 672*3 = 2016 pairs exactly
#define NW  (NT / 32)
#define NG  10             // row groups for m^2 phases (threads 0..639)
#define OBJ 10
#define NPAIRS 2016        // 64*63/2 off-diagonal pairs (j<k)
#define PPT 3

// Exact-semantics eval (handles y<0 via floor like the reference):
// y=16x; idx=trunc(y); fr=y-floor(y); val=csum[idx]+fr*w[min(idx+1,16)]
// Table t[idx] = (csum[idx], w_next[idx]).
__device__ __forceinline__ float plin_eval(const float2* __restrict__ t, float x) {
    float y  = 16.0f * x;
    int  idx = (int)y;
    float fr = y - floorf(y);
    float2 v = t[idx];
    return fmaf(fr, v.y, v.x);
}

// Fused fast eval for y guaranteed in [0,16]:
// val = T0[idx] + y*T1[idx], with T0 = csum - idx*w_next, T1 = w_next.
// Table replicated per lane: entries strided by 32 -> conflict-free LDS.64.
__device__ __forceinline__ float plin_fused_rep(const float2* __restrict__ t, float y) {
    int idx = (int)y;
    float2 v = t[idx * 32];
    return fmaf(y, v.y, v.x);
}

__global__ __launch_bounds__(NT, 1)
void counter_kernel(const float* __restrict__ boxes,   // (n,4,64)
                    const float* __restrict__ attn,    // (n,64)
                    const float* __restrict__ fw,      // (16,17)
                    float* __restrict__ out)           // (n,11)
{
    __shared__ float2 tab[8][NPW + 1];          // (csum, w_next)
    __shared__ float2 rep2[(NPW + 1) * 32];     // fused f2 table, lane-replicated
    __shared__ float  ds[M * M];                // dedup scores, PRE-SCALED by 16
    __shared__ float  sim[M * M];
    __shared__ unsigned short pairs[NPAIRS];    // packed (j | k<<8)
    __shared__ float  att_s[M], area_s[M];
    __shared__ float  bx1[M], by1[M], bx2[M], by2[M];
    __shared__ float  part[NG * M];
    __shared__ float  rowinv[M];
    __shared__ float  wredA[NW], wredB[NW];

    const int tid = threadIdx.x;
    const int bi  = blockIdx.x;

    // ---- Phase 0: build plin tables ----
    if (tid < 8) {
        const int fn = tid;
        float w[NPW + 1];
        float s = 0.0f;
        #pragma unroll
        for (int i = 0; i <= NPW; i++) { w[i] = fabsf(fw[fn * (NPW + 1) + i]); s += w[i]; }
        #pragma unroll
        for (int i = 0; i <= NPW; i++) w[i] = w[i] / s;
        float c = 0.0f;
        #pragma unroll
        for (int i = 0; i <= NPW; i++) {
            c += w[i];
            float wn = w[(i + 1 <= NPW) ? (i + 1) : NPW];
            tab[fn][i] = make_float2(c, wn);
        }
    }
    __syncthreads();

    // ---- Phase 1: fused replicated f2 table, pair table, inputs ----
    for (int e = tid; e < (NPW + 1) * 32; e += NT) {
        int i = e >> 5;
        float2 v = tab[2][i];
        // fused form: T0 = csum - idx*w_next, T1 = w_next
        rep2[e] = make_float2(fmaf(-(float)i, v.y, v.x), v.y);
    }

    // pairs diagonal-major: d=1..63, j=0..63-d, k=j+d -> lane-consecutive j,k
    for (int p = tid; p < NPAIRS; p += NT) {
        int j = 0, k = 0, cum = 0;
        for (int d = 1; d < 64; d++) {
            int len = 64 - d;
            if (p < cum + len) { j = p - cum; k = j + d; break; }
            cum += len;
        }
        pairs[p] = (unsigned short)(j | (k << 8));
    }

    if (tid < M) {
        const int j = tid;
        att_s[j] = attn[bi * M + j];
        float x1 = boxes[(bi * 4 + 0) * M + j];
        float y1 = boxes[(bi * 4 + 1) * M + j];
        float x2 = boxes[(bi * 4 + 2) * M + j];
        float y2 = boxes[(bi * 4 + 3) * M + j];
        bx1[j] = x1; by1[j] = y1; bx2[j] = x2; by2[j] = y2;
        area_s[j] = fmaxf(x2 - x1, 0.0f) * fmaxf(y2 - y1, 0.0f);
    }
    __syncthreads();

    // ---- Phase 2: ds16 = 16*f3(rel)*f4(dist), dconf, attconf, sim diag ----
    const int c = tid & 63;
    const int g = tid >> 6;        // 0..10 (g==10: warp 20 upper half, skips m^2 loops)
    const float attc = att_s[c];
    const float x2c = bx2[c], y2c = by2[c], x1c = bx1[c], y1c = by1[c], arc = area_s[c];

    float attconf = 0.0f;
    if (tid < M)
        attconf = fabsf(plin_eval(tab[5], att_s[tid]) - 0.5f);

    float dconf_local = 0.0f;
    if (g < NG) {
        for (int r = g; r < M; r += NG) {
            float rel  = att_s[r] * attc;
            float ix = fminf(bx2[r], x2c) - fmaxf(bx1[r], x1c);
            float iy = fminf(by2[r], y2c) - fmaxf(by1[r], y1c);
            ix = fmaxf(ix, 0.0f); iy = fmaxf(iy, 0.0f);
            float inter = ix * iy;
            float dist  = 1.0f - inter / (area_s[r] + arc - inter + 1e-12f);

            ds[r * M + c] = 16.0f * (plin_eval(tab[3], rel) * plin_eval(tab[4], dist));
            dconf_local += fabsf(plin_eval(tab[6], dist) - 0.5f);
        }
    }

    // sim diagonal: f2(1)^65 = csum2[16]^65
    if (tid < M) {
        float2 v16 = tab[2][NPW];
        float cv  = v16.x;                  // csum[16]
        float c2  = cv * cv;
        float c4  = c2 * c2;
        float c8  = c4 * c4;
        float c16 = c8 * c8;
        float c32 = c16 * c16;
        float c64 = c32 * c32;
        sim[tid * M + tid] = c64 * cv;
    }
    __syncthreads();

    // ---- Phase 3: hot m^3 loop over 2016 pairs, 3 per thread, zero waste ----
    int jj[PPT], kk[PPT];
    #pragma unroll
    for (int q = 0; q < PPT; q++) {
        unsigned short pk = pairs[tid + NT * q];
        jj[q] = pk & 255;
        kk[q] = pk >> 8;
    }

    float prod[PPT];
    #pragma unroll
    for (int q = 0; q < PPT; q++) prod[q] = 1.0f;

    const float2* trep = rep2 + (tid & 31);

    #pragma unroll 4
    for (int l = 0; l < M; l++) {
        const float* __restrict__ row = ds + l * M;
        #pragma unroll
        for (int q = 0; q < PPT; q++) {
            float a = row[jj[q]];
            float b = row[kk[q]];
            float y = 16.0f - fabsf(a - b);      // in (0,16]
            prod[q] *= plin_fused_rep(trep, y);
        }
    }

    #pragma unroll
    for (int q = 0; q < PPT; q++) {
        const int j = jj[q], k = kk[q];
        float ad = fabsf(att_s[j] - att_s[k]);
        float y  = fmaf(-16.0f, ad, 16.0f);      // in (0,16]
        float sv = prod[q] * plin_fused_rep(trep, y);
        sim[j * M + k] = sv;
        sim[k * M + j] = sv;
    }
    __syncthreads();

    // ---- Phase 4: row sums (column-wise reads) -> rowinv ----
    if (g < NG) {
        float s = 0.0f;
        for (int k = g; k < M; k += NG)
            s += sim[k * M + c];
        part[g * M + c] = s;
    }
    __syncthreads();
    if (tid < M) {
        float rs = 0.0f;
        #pragma unroll
        for (int gg = 0; gg < NG; gg++) rs += part[gg * M + tid];
        rowinv[tid] = 1.0f / rs;
    }
    __syncthreads();

    // ---- Phase 5: recompute A = f0*f1, accumulate score ----
    float accA = 0.0f;
    if (g < NG) {
        for (int r = g; r < M; r += NG) {
            float rel  = att_s[r] * attc;
            float ix = fminf(bx2[r], x2c) - fmaxf(bx1[r], x1c);
            float iy = fminf(by2[r], y2c) - fmaxf(by1[r], y1c);
            ix = fmaxf(ix, 0.0f); iy = fmaxf(iy, 0.0f);
            float inter = ix * iy;
            float dist  = 1.0f - inter / (area_s[r] + arc - inter + 1e-12f);
            float Av = plin_eval(tab[0], rel) * plin_eval(tab[1], dist);
            accA += Av * rowinv[r];
        }
        accA *= rowinv[c];
    }

    float corr = 0.0f;
    if (tid < M) {
        float a = att_s[tid];
        corr = plin_eval(tab[0], a * a) * rowinv[tid];
    }

    float ra  = accA + corr;
    float rbv = dconf_local * (1.0f / 4096.0f) + attconf * (1.0f / 64.0f);

    #pragma unroll
    for (int off = 16; off > 0; off >>= 1) {
        ra  += __shfl_down_sync(0xffffffffu, ra,  off);
        rbv += __shfl_down_sync(0xffffffffu, rbv, off);
    }
    if ((tid & 31) == 0) {
        wredA[tid >> 5] = ra;
        wredB[tid >> 5] = rbv;
    }
    __syncthreads();

    // ---- Phase 6: score -> one-hot * conf ----
    if (tid == 0) {
        float S = 0.0f, B = 0.0f;
        #pragma unroll
        for (int i = 0; i < NW; i++) { S += wredA[i]; B += wredB[i]; }

        float score = sqrtf(S + 1e-20f);
        float conf  = plin_eval(tab[7], B);

        float sc  = fminf(fmaxf(score, 0.0f), (float)OBJ);
        int   i0  = (int)sc;
        float fr  = sc - floorf(sc);
        int   i1  = (i0 + 1 <= OBJ) ? (i0 + 1) : OBJ;

        #pragma unroll
        for (int o = 0; o <= OBJ; o++) {
            float v = 0.0f;
            if (o == i0) v += (1.0f - fr);
            if (o == i1) v += fr;
            out[bi * (OBJ + 1) + o] = conf * v;
        }
    }
}

extern "C" void kernel_launch(void* const* d_in, const int* in_sizes, int n_in,
                              void* d_out, int out_size) {
    const float* boxes = (const float*)d_in[0];   // (n,4,64)
    const float* attn  = (const float*)d_in[1];   // (n,64)
    const float* fwts  = (const float*)d_in[2];   // (16,17)
    float* out = (float*)d_out;                   // (n,11)

    const int n = in_sizes[1] / M;                // 128
    counter_kernel<<<n, NT>>>(boxes, attn, fwts, out);
}

// round 7
// speedup vs baseline: 1.0960x; 1.0960x over previous
#include <cuda_runtime.h>
#include <cuda_bf16.h>
#include <stdint.h>

#define NPW 16
#define M   64
#define NT  672            // 21 warps; 672*3 = 2016 pairs exactly
#define NW  (NT / 32)
#define NG  10
#define OBJ 10
#define NPAIRS 2016
#define PPT 3

// Dynamic shared memory layout (bytes)
#define OFF_DS    0u          // 16384  ds[r*M+c], pre-scaled by 16
#define OFF_SIM   16384u      // 16384
#define OFF_AM    32768u      // 16384
#define OFF_REP2  49152u      // float2[17*32] = 4352 (fused hot f2 table, lane-replicated)
#define OFF_TAB   53504u      // float2[8*17]  = 1088 (csum, w_next)
#define OFF_ATT   54592u
#define OFF_AREA  54848u
#define OFF_BX1   55104u
#define OFF_BY1   55360u
#define OFF_BX2   55616u
#define OFF_BY2   55872u
#define OFF_PART  56128u      // NG*64*4 = 2560
#define OFF_RINV  58688u
#define OFF_WRA   58944u
#define OFF_WRB   59040u
#define SMEM_TOTAL 59136u

// Exact-semantics eval (reference: idx = trunc(16x); fr = 16x - floor(16x)):
__device__ __forceinline__ float plin_eval(const float2* __restrict__ t, float x) {
    float y  = 16.0f * x;
    int  idx = (int)y;
    float fr = y - floorf(y);
    float2 v = t[idx];
    return fmaf(fr, v.y, v.x);
}

// Fused fast eval for y guaranteed in [0,16]:
// val = T0[idx] + y*T1[idx], T0 = csum - idx*w_next, T1 = w_next.
// Table replicated per lane: entries strided by 32 -> conflict-free LDS.64.
__device__ __forceinline__ float plin_fused_rep(const float2* __restrict__ t, float y) {
    int idx = (int)y;
    float2 v = t[idx * 32];
    return fmaf(y, v.y, v.x);
}

__global__ __launch_bounds__(NT, 1)
void counter_kernel(const float* __restrict__ boxes,   // (n,4,64)
                    const float* __restrict__ attn,    // (n,64)
                    const float* __restrict__ fw,      // (16,17)
                    float* __restrict__ out)           // (n,11)
{
    extern __shared__ char smem[];
    const int tid  = threadIdx.x;
    const int bi   = blockIdx.x;
    const int lane = tid & 31;
    const int wid  = tid >> 5;
    const unsigned FULL = 0xffffffffu;

    float*  ds     = (float*)(smem + OFF_DS);
    float*  sim    = (float*)(smem + OFF_SIM);
    float*  Am     = (float*)(smem + OFF_AM);
    float2* rep2   = (float2*)(smem + OFF_REP2);
    float2* tab    = (float2*)(smem + OFF_TAB);   // tab[fn*17 + i]
    float*  att_s  = (float*)(smem + OFF_ATT);
    float*  area_s = (float*)(smem + OFF_AREA);
    float*  sbx1   = (float*)(smem + OFF_BX1);
    float*  sby1   = (float*)(smem + OFF_BY1);
    float*  sbx2   = (float*)(smem + OFF_BX2);
    float*  sby2   = (float*)(smem + OFF_BY2);
    float*  part   = (float*)(smem + OFF_PART);
    float*  rowinv = (float*)(smem + OFF_RINV);
    float*  wredA  = (float*)(smem + OFF_WRA);
    float*  wredB  = (float*)(smem + OFF_WRB);

    // ---- Phase 0: build plin tables (fns 0..7); proven R4 path ----
    if (tid < 8) {
        const int fn = tid;
        float w[NPW + 1];
        float s = 0.0f;
        #pragma unroll
        for (int i = 0; i <= NPW; i++) { w[i] = fabsf(fw[fn * 17 + i]); s += w[i]; }
        #pragma unroll
        for (int i = 0; i <= NPW; i++) w[i] = w[i] / s;
        float c = 0.0f;
        #pragma unroll
        for (int i = 0; i <= NPW; i++) {
            c += w[i];
            float wn = w[(i + 1 <= NPW) ? (i + 1) : NPW];
            tab[fn * 17 + i] = make_float2(c, wn);
        }
    }

    if (tid < M) {
        const int j = tid;
        att_s[j] = attn[bi * M + j];
        float x1 = boxes[(bi * 4 + 0) * M + j];
        float y1 = boxes[(bi * 4 + 1) * M + j];
        float x2 = boxes[(bi * 4 + 2) * M + j];
        float y2 = boxes[(bi * 4 + 3) * M + j];
        sbx1[j] = x1; sby1[j] = y1; sbx2[j] = x2; sby2[j] = y2;
        area_s[j] = fmaxf(x2 - x1, 0.0f) * fmaxf(y2 - y1, 0.0f);
    }
    __syncthreads();

    // ---- Phase 1: fused lane-replicated f2 table ----
    for (int e = tid; e < (NPW + 1) * 32; e += NT) {
        int i = e >> 5;
        float2 v = tab[2 * 17 + i];
        rep2[e] = make_float2(fmaf(-(float)i, v.y, v.x), v.y);
    }
    __syncthreads();

    // ---- Phase 2: ds16, Am = f0*f1, dconf, attconf, sim diagonal ----
    const int c = tid & 63;
    const int g = tid >> 6;                        // 0..10
    const float attc = att_s[c];
    const float x1c = sbx1[c], y1c = sby1[c], x2c = sbx2[c], y2c = sby2[c];
    const float arc = area_s[c];

    float attconf = 0.0f;
    if (tid < M)
        attconf = fabsf(plin_eval(tab + 5 * 17, att_s[tid]) - 0.5f);

    float dconf = 0.0f;
    if (g < NG) {
        for (int r = g; r < M; r += NG) {
            float rel = att_s[r] * attc;
            float ix = fminf(sbx2[r], x2c) - fmaxf(sbx1[r], x1c);
            float iy = fminf(sby2[r], y2c) - fmaxf(sby1[r], y1c);
            ix = fmaxf(ix, 0.0f); iy = fmaxf(iy, 0.0f);
            float inter = ix * iy;
            float den   = area_s[r] + arc - inter + 1e-12f;
            float dist  = 1.0f - inter / den;

            float f0v = plin_eval(tab + 0 * 17, rel);
            float f1v = plin_eval(tab + 1 * 17, dist);
            float f3v = plin_eval(tab + 3 * 17, rel);
            float f4v = plin_eval(tab + 4 * 17, dist);
            float f6v = plin_eval(tab + 6 * 17, dist);

            Am[r * M + c] = f0v * f1v;
            ds[r * M + c] = 16.0f * (f3v * f4v);
            dconf += fabsf(f6v - 0.5f);
        }
    }

    // sim diagonal: f2(1)^65 = csum2[16]^65 (pow ladder)
    if (tid < M) {
        float cv  = tab[2 * 17 + NPW].x;
        float c2  = cv * cv;
        float c4  = c2 * c2;
        float c8  = c4 * c4;
        float c16 = c8 * c8;
        float c32 = c16 * c16;
        float c64 = c32 * c32;
        sim[tid * M + tid] = c64 * cv;
    }
    __syncthreads();

    // ---- Phase 3: hot m^3 loop, 2016 symmetric pairs, 3/thread ----
    // Closed-form diagonal-major decode. __fsqrt_rn is exact at the
    // perfect-square group boundaries; interior margin >= 0.016.
    int jj[PPT], kk[PPT];
    #pragma unroll
    for (int q = 0; q < PPT; q++) {
        int p = tid + NT * q;
        float disc = 16129.0f - 8.0f * (float)p;
        int d = (int)((129.0f - __fsqrt_rn(disc)) * 0.5f);
        d = (d < 1) ? 1 : ((d > 63) ? 63 : d);
        int j = p - (((d - 1) * (128 - d)) >> 1);
        j = (j < 0) ? 0 : ((j > 63 - d) ? (63 - d) : j);
        jj[q] = j;
        kk[q] = j + d;
    }

    float prod[PPT] = {1.0f, 1.0f, 1.0f};
    const float2* trep = rep2 + (tid & 31);

    #pragma unroll 4
    for (int l = 0; l < M; l++) {
        const float* __restrict__ row = ds + l * M;
        #pragma unroll
        for (int q = 0; q < PPT; q++) {
            float a = row[jj[q]];
            float b = row[kk[q]];
            float y = 16.0f - fabsf(a - b);      // in (0,16]
            prod[q] *= plin_fused_rep(trep, y);
        }
    }

    #pragma unroll
    for (int q = 0; q < PPT; q++) {
        const int j = jj[q], k = kk[q];
        float ad = fabsf(att_s[j] - att_s[k]);
        float y  = fmaf(-16.0f, ad, 16.0f);      // in (0,16]
        float sv = prod[q] * plin_fused_rep(trep, y);
        sim[j * M + k] = sv;
        sim[k * M + j] = sv;
    }
    __syncthreads();

    // ---- Phase 4: row sums (column-wise reads) -> rowinv ----
    if (g < NG) {
        float s = 0.0f;
        for (int k = g; k < M; k += NG)
            s += sim[k * M + c];
        part[g * M + c] = s;
    }
    __syncthreads();
    if (tid < M) {
        float rs = 0.0f;
        #pragma unroll
        for (int gg = 0; gg < NG; gg++) rs += part[gg * M + tid];
        rowinv[tid] = 1.0f / rs;
    }
    __syncthreads();

    // ---- Phase 5: score accumulation (Am reused; no IoU/eval recompute) ----
    float accA = 0.0f;
    if (g < NG) {
        for (int r = g; r < M; r += NG)
            accA += Am[r * M + c] * rowinv[r];
        accA *= rowinv[c];
    }

    float corr = 0.0f;
    if (tid < M) {
        float a = att_s[tid];
        corr = plin_eval(tab + 0 * 17, a * a) * rowinv[tid];
    }

    float ra  = accA + corr;
    float rbv = dconf * (1.0f / 4096.0f) + attconf * (1.0f / 64.0f);
    #pragma unroll
    for (int off = 16; off > 0; off >>= 1) {
        ra  += __shfl_down_sync(FULL, ra,  off);
        rbv += __shfl_down_sync(FULL, rbv, off);
    }
    if (lane == 0) { wredA[wid] = ra; wredB[wid] = rbv; }
    __syncthreads();

    // ---- Phase 6: score -> one-hot * conf ----
    if (tid == 0) {
        float S = 0.0f, B = 0.0f;
        #pragma unroll
        for (int i = 0; i < NW; i++) { S += wredA[i]; B += wredB[i]; }

        float score = sqrtf(S + 1e-20f);
        float conf  = plin_eval(tab + 7 * 17, B);

        float sc = fminf(fmaxf(score, 0.0f), (float)OBJ);
        int   i0 = (int)sc;
        float fr = sc - floorf(sc);
        int   i1 = (i0 + 1 <= OBJ) ? (i0 + 1) : OBJ;

        #pragma unroll
        for (int o = 0; o <= OBJ; o++) {
            float v = 0.0f;
            if (o == i0) v += (1.0f - fr);
            if (o == i1) v += fr;
            out[bi * (OBJ + 1) + o] = conf * v;
        }
    }
}

extern "C" void kernel_launch(void* const* d_in, const int* in_sizes, int n_in,
                              void* d_out, int out_size) {
    const float* boxes = (const float*)d_in[0];   // (n,4,64)
    const float* attn  = (const float*)d_in[1];   // (n,64)
    const float* fwts  = (const float*)d_in[2];   // (16,17)
    float* out = (float*)d_out;                   // (n,11)

    cudaFuncSetAttribute(counter_kernel,
                         cudaFuncAttributeMaxDynamicSharedMemorySize, SMEM_TOTAL);

    const int n = in_sizes[1] / M;                // 128
    counter_kernel<<<n, NT, SMEM_TOTAL>>>(boxes, attn, fwts, out);
}